// round 3
// baseline (speedup 1.0000x reference)
#include <cuda_runtime.h>
#include <math.h>

// ---------------- problem constants ----------------
#define Dm   1024
#define Tn   1024
#define Bb   2
#define Hh   16
#define HDd  64
#define Ll   4
#define DFF  4096
#define VOCAB 16384
#define BT   (Bb*Tn)          // 2048 token rows

// ---------------- scratch (no allocations allowed) ----------------
__device__ float g_x [BT*Dm];
__device__ float g_h [BT*Dm];
__device__ float g_q [BT*Dm];
__device__ float g_k [BT*Dm];
__device__ float g_v [BT*Dm];
__device__ float g_vT[BT*Dm];                 // [B,H,HD,T]
__device__ float g_o [BT*Dm];
__device__ float g_sc[(size_t)Bb*Hh*Tn*Tn];   // 128 MB scores [B,H,T,T]
__device__ float g_g1[BT*DFF];
__device__ float g_g3[BT*DFF];
__device__ float g_cos[BT*32];
__device__ float g_sin[BT*32];

// ---------------- generic batched NT SGEMM: C = A[M,K] * B[N,K]^T ----------------
// batch z = b*Hbat + h, with separate (b,h) strides for A,B,C.
// beta=1 -> accumulate into C (residual add), beta=0 -> overwrite.
__global__ __launch_bounds__(256, 2)
void gemm_nt(const float* __restrict__ A, const float* __restrict__ B, float* __restrict__ C,
             int M, int N, int K, int lda, int ldb, int ldc,
             long long sAb, long long sAh, long long sBb, long long sBh,
             long long sCb, long long sCh, int Hbat, int beta)
{
    int z = blockIdx.z;
    int b = z / Hbat, h = z - b * Hbat;
    A += (long long)b * sAb + (long long)h * sAh;
    B += (long long)b * sBb + (long long)h * sBh;
    C += (long long)b * sCb + (long long)h * sCh;

    __shared__ float As[8][128];
    __shared__ float Bs[8][128];

    const int tid = threadIdx.x;
    const int m0 = blockIdx.y * 128;
    const int n0 = blockIdx.x * 128;
    const int lr = tid >> 1;           // 0..127
    const int lc = (tid & 1) * 4;      // 0 or 4
    const int ty = tid >> 4;           // 0..15 -> 8 rows
    const int tx = tid & 15;           // 0..15 -> 8 cols

    float acc[8][8];
#pragma unroll
    for (int i = 0; i < 8; i++)
#pragma unroll
        for (int j = 0; j < 8; j++) acc[i][j] = 0.f;

    const int mA = m0 + lr;
    const int nB = n0 + lr;

    for (int k0 = 0; k0 < K; k0 += 8) {
        float4 av = make_float4(0.f, 0.f, 0.f, 0.f);
        float4 bv = make_float4(0.f, 0.f, 0.f, 0.f);
        if (mA < M) av = *reinterpret_cast<const float4*>(A + (long long)mA * lda + k0 + lc);
        if (nB < N) bv = *reinterpret_cast<const float4*>(B + (long long)nB * ldb + k0 + lc);
        __syncthreads();
        As[lc + 0][lr] = av.x; As[lc + 1][lr] = av.y; As[lc + 2][lr] = av.z; As[lc + 3][lr] = av.w;
        Bs[lc + 0][lr] = bv.x; Bs[lc + 1][lr] = bv.y; Bs[lc + 2][lr] = bv.z; Bs[lc + 3][lr] = bv.w;
        __syncthreads();
#pragma unroll
        for (int kk = 0; kk < 8; kk++) {
            float4 a0 = *reinterpret_cast<const float4*>(&As[kk][ty * 8]);
            float4 a1 = *reinterpret_cast<const float4*>(&As[kk][ty * 8 + 4]);
            float4 b0 = *reinterpret_cast<const float4*>(&Bs[kk][tx * 8]);
            float4 b1 = *reinterpret_cast<const float4*>(&Bs[kk][tx * 8 + 4]);
            float ra[8] = {a0.x, a0.y, a0.z, a0.w, a1.x, a1.y, a1.z, a1.w};
            float rb[8] = {b0.x, b0.y, b0.z, b0.w, b1.x, b1.y, b1.z, b1.w};
#pragma unroll
            for (int i = 0; i < 8; i++)
#pragma unroll
                for (int j = 0; j < 8; j++)
                    acc[i][j] += ra[i] * rb[j];
        }
    }

#pragma unroll
    for (int i = 0; i < 8; i++) {
        int m = m0 + ty * 8 + i;
        if (m >= M) continue;
        int n = n0 + tx * 8;
        if (n >= N) continue;                 // N always multiple of 8
        float* cp = C + (long long)m * ldc + n;
        if (beta) {
#pragma unroll
            for (int j = 0; j < 8; j++) acc[i][j] += cp[j];
        }
        *reinterpret_cast<float4*>(cp)     = make_float4(acc[i][0], acc[i][1], acc[i][2], acc[i][3]);
        *reinterpret_cast<float4*>(cp + 4) = make_float4(acc[i][4], acc[i][5], acc[i][6], acc[i][7]);
    }
}

// ---------------- embedding gather ----------------
__global__ __launch_bounds__(256)
void gather_k(const int* __restrict__ tok, const float* __restrict__ embed, float* __restrict__ x)
{
    int bt = blockIdx.x;
    int t = tok[bt];
    reinterpret_cast<float4*>(x + (long long)bt * Dm)[threadIdx.x] =
        reinterpret_cast<const float4*>(embed + (long long)t * Dm)[threadIdx.x];
}

// ---------------- RoPE tables (match JAX fp32 pipeline) ----------------
__global__ __launch_bounds__(256)
void rope_tables_k(const int* __restrict__ pos, float* __restrict__ cosT, float* __restrict__ sinT)
{
    int idx = blockIdx.x * blockDim.x + threadIdx.x;   // BT*32
    if (idx >= BT * 32) return;
    int i = idx & 31;
    int bt = idx >> 5;
    float t = (float)(2 * i) / 64.0f;
    float u = (float)pow(10000.0, (double)t);          // correctly-rounded fp32 pow
    float inv = 1.0f / u;
    float ang = (float)pos[bt] * inv;                  // fp32 angle, same as JAX
    cosT[idx] = (float)cos((double)ang);               // correctly-rounded fp32 cos of fp32 angle
    sinT[idx] = (float)sin((double)ang);
}

// ---------------- apply RoPE in place on q or k ----------------
__global__ __launch_bounds__(256)
void rope_apply_k(float* __restrict__ q, const float* __restrict__ cosT, const float* __restrict__ sinT)
{
    int idx = blockIdx.x * blockDim.x + threadIdx.x;   // BT*H*32
    if (idx >= BT * Hh * 32) return;
    int i  = idx & 31;
    int r  = idx >> 5;
    int hh = r & 15;
    int bt = r >> 4;
    float c = cosT[bt * 32 + i];
    float s = sinT[bt * 32 + i];
    float* p = q + (long long)bt * Dm + hh * HDd + 2 * i;
    float xr = p[0], xi = p[1];
    p[0] = xr * c - xi * s;
    p[1] = xr * s + xi * c;
}

// ---------------- RMSNorm (one block per row of 1024) ----------------
__global__ __launch_bounds__(256)
void rmsnorm_k(const float* __restrict__ x, const float* __restrict__ w, float* __restrict__ h)
{
    int row = blockIdx.x;
    float4 v = reinterpret_cast<const float4*>(x + (long long)row * Dm)[threadIdx.x];
    float ss = v.x * v.x + v.y * v.y + v.z * v.z + v.w * v.w;
#pragma unroll
    for (int o = 16; o > 0; o >>= 1) ss += __shfl_xor_sync(0xffffffffu, ss, o);
    __shared__ float red[8];
    __shared__ float rinv;
    if ((threadIdx.x & 31) == 0) red[threadIdx.x >> 5] = ss;
    __syncthreads();
    if (threadIdx.x == 0) {
        float s = 0.f;
#pragma unroll
        for (int i = 0; i < 8; i++) s += red[i];
        rinv = rsqrtf(s * (1.0f / Dm) + 1e-6f);
    }
    __syncthreads();
    float r = rinv;
    float4 wv = reinterpret_cast<const float4*>(w)[threadIdx.x];
    float4 o4 = make_float4(v.x * r * wv.x, v.y * r * wv.y, v.z * r * wv.z, v.w * r * wv.w);
    reinterpret_cast<float4*>(h + (long long)row * Dm)[threadIdx.x] = o4;
}

// ---------------- transpose v -> vT[b,h,hd,t] ----------------
__global__ __launch_bounds__(256)
void transpose_v_k(const float* __restrict__ v, float* __restrict__ vT)
{
    long long idx = (long long)blockIdx.x * blockDim.x + threadIdx.x;  // BT*Dm = 2M
    if (idx >= (long long)BT * Dm) return;
    int t  = (int)(idx & (Tn - 1));
    long long r = idx >> 10;
    int hd = (int)(r & (HDd - 1)); r >>= 6;
    int hh = (int)(r & (Hh - 1));
    int b  = (int)(r >> 4);
    vT[idx] = v[((long long)(b * Tn + t)) * Dm + hh * HDd + hd];
}

// ---------------- softmax over rows of 1024 (scale folded in) ----------------
__global__ __launch_bounds__(256)
void softmax_k(float* __restrict__ sc)
{
    long long row = blockIdx.x;
    float4* p = reinterpret_cast<float4*>(sc + row * Tn);
    int tid = threadIdx.x;
    float4 v = p[tid];
    const float scale = 0.125f;                 // 1/sqrt(64)
    v.x *= scale; v.y *= scale; v.z *= scale; v.w *= scale;
    float m = fmaxf(fmaxf(v.x, v.y), fmaxf(v.z, v.w));
#pragma unroll
    for (int o = 16; o > 0; o >>= 1) m = fmaxf(m, __shfl_xor_sync(0xffffffffu, m, o));
    __shared__ float red[8];
    __shared__ float bc;
    if ((tid & 31) == 0) red[tid >> 5] = m;
    __syncthreads();
    if (tid == 0) {
        float mm = red[0];
#pragma unroll
        for (int i = 1; i < 8; i++) mm = fmaxf(mm, red[i]);
        bc = mm;
    }
    __syncthreads();
    m = bc;
    float e0 = expf(v.x - m), e1 = expf(v.y - m), e2 = expf(v.z - m), e3 = expf(v.w - m);
    float s = e0 + e1 + e2 + e3;
#pragma unroll
    for (int o = 16; o > 0; o >>= 1) s += __shfl_xor_sync(0xffffffffu, s, o);
    __syncthreads();
    if ((tid & 31) == 0) red[tid >> 5] = s;
    __syncthreads();
    if (tid == 0) {
        float t = 0.f;
#pragma unroll
        for (int i = 0; i < 8; i++) t += red[i];
        bc = 1.0f / t;
    }
    __syncthreads();
    float inv = bc;
    p[tid] = make_float4(e0 * inv, e1 * inv, e2 * inv, e3 * inv);
}

// ---------------- g1 = silu(g1) * g3 ----------------
__global__ __launch_bounds__(256)
void silu_mul_k(float* __restrict__ g1, const float* __restrict__ g3)
{
    long long idx = (long long)blockIdx.x * blockDim.x + threadIdx.x;  // float4 count
    if (idx >= (long long)BT * DFF / 4) return;
    float4 a = reinterpret_cast<float4*>(g1)[idx];
    float4 b = reinterpret_cast<const float4*>(g3)[idx];
    a.x = (a.x / (1.f + expf(-a.x))) * b.x;
    a.y = (a.y / (1.f + expf(-a.y))) * b.y;
    a.z = (a.z / (1.f + expf(-a.z))) * b.z;
    a.w = (a.w / (1.f + expf(-a.w))) * b.w;
    reinterpret_cast<float4*>(g1)[idx] = a;
}

// ---------------- host orchestration ----------------
static inline void launch_gemm(const float* A, const float* B, float* C,
                               int M, int N, int K, int lda, int ldb, int ldc,
                               long long sAb, long long sAh, long long sBb, long long sBh,
                               long long sCb, long long sCh, int Hbat, int nbat, int beta)
{
    dim3 grid((N + 127) / 128, (M + 127) / 128, nbat);
    gemm_nt<<<grid, 256>>>(A, B, C, M, N, K, lda, ldb, ldc,
                           sAb, sAh, sBb, sBh, sCb, sCh, Hbat, beta);
}

extern "C" void kernel_launch(void* const* d_in, const int* in_sizes, int n_in,
                              void* d_out, int out_size)
{
    const int*   tok         = (const int*)d_in[0];
    const int*   pos         = (const int*)d_in[1];
    const float* embed       = (const float*)d_in[2];
    const float* attn_norm_w = (const float*)d_in[3];
    const float* wq          = (const float*)d_in[4];
    const float* wk          = (const float*)d_in[5];
    const float* wv          = (const float*)d_in[6];
    const float* wo          = (const float*)d_in[7];
    const float* ff_norm_w   = (const float*)d_in[8];
    const float* w1          = (const float*)d_in[9];
    const float* w2          = (const float*)d_in[10];
    const float* w3          = (const float*)d_in[11];
    const float* norm_w      = (const float*)d_in[12];
    float* out = (float*)d_out;

    float *x, *h, *q, *k, *v, *vT, *o, *sc, *g1, *g3, *ct, *st;
    cudaGetSymbolAddress((void**)&x,  g_x);
    cudaGetSymbolAddress((void**)&h,  g_h);
    cudaGetSymbolAddress((void**)&q,  g_q);
    cudaGetSymbolAddress((void**)&k,  g_k);
    cudaGetSymbolAddress((void**)&v,  g_v);
    cudaGetSymbolAddress((void**)&vT, g_vT);
    cudaGetSymbolAddress((void**)&o,  g_o);
    cudaGetSymbolAddress((void**)&sc, g_sc);
    cudaGetSymbolAddress((void**)&g1, g_g1);
    cudaGetSymbolAddress((void**)&g3, g_g3);
    cudaGetSymbolAddress((void**)&ct, g_cos);
    cudaGetSymbolAddress((void**)&st, g_sin);

    gather_k<<<BT, 256>>>(tok, embed, x);
    rope_tables_k<<<(BT * 32 + 255) / 256, 256>>>(pos, ct, st);

    const long long DD = (long long)Dm * Dm;
    for (int l = 0; l < Ll; l++) {
        // ---- attention ----
        rmsnorm_k<<<BT, 256>>>(x, attn_norm_w + (long long)l * Dm, h);
        launch_gemm(h, wq + l * DD, q, BT, Dm, Dm, Dm, Dm, Dm, 0,0,0,0,0,0, 1, 1, 0);
        launch_gemm(h, wk + l * DD, k, BT, Dm, Dm, Dm, Dm, Dm, 0,0,0,0,0,0, 1, 1, 0);
        launch_gemm(h, wv + l * DD, v, BT, Dm, Dm, Dm, Dm, Dm, 0,0,0,0,0,0, 1, 1, 0);
        rope_apply_k<<<(BT * Hh * 32 + 255) / 256, 256>>>(q, ct, st);
        rope_apply_k<<<(BT * Hh * 32 + 255) / 256, 256>>>(k, ct, st);
        transpose_v_k<<<(BT * Dm + 255) / 256, 256>>>(v, vT);
        // scores[b,h,t,s] = q . k  (batched over 32 (b,h))
        launch_gemm(q, k, sc, Tn, Tn, HDd, Dm, Dm, Tn,
                    (long long)Tn * Dm, HDd, (long long)Tn * Dm, HDd,
                    (long long)Hh * Tn * Tn, (long long)Tn * Tn, Hh, Bb * Hh, 0);
        softmax_k<<<Bb * Hh * Tn, 256>>>(sc);
        // o[b,t,h,hd] = scores . vT
        launch_gemm(sc, vT, o, Tn, HDd, Tn, Tn, Tn, Dm,
                    (long long)Hh * Tn * Tn, (long long)Tn * Tn,
                    (long long)Hh * HDd * Tn, (long long)HDd * Tn,
                    (long long)Tn * Dm, HDd, Hh, Bb * Hh, 0);
        // x += o * wo^T
        launch_gemm(o, wo + l * DD, x, BT, Dm, Dm, Dm, Dm, Dm, 0,0,0,0,0,0, 1, 1, 1);
        // ---- SwiGLU FFN ----
        rmsnorm_k<<<BT, 256>>>(x, ff_norm_w + (long long)l * Dm, h);
        launch_gemm(h, w1 + (long long)l * DFF * Dm, g1, BT, DFF, Dm, Dm, Dm, DFF, 0,0,0,0,0,0, 1, 1, 0);
        launch_gemm(h, w3 + (long long)l * DFF * Dm, g3, BT, DFF, Dm, Dm, Dm, DFF, 0,0,0,0,0,0, 1, 1, 0);
        silu_mul_k<<<(BT * DFF / 4 + 255) / 256, 256>>>(g1, g3);
        // x += g1 * w2^T  (w2 is [D, DFF])
        launch_gemm(g1, w2 + (long long)l * Dm * DFF, x, BT, Dm, DFF, DFF, DFF, Dm, 0,0,0,0,0,0, 1, 1, 1);
    }

    // ---- final norm + tied LM head ----
    rmsnorm_k<<<BT, 256>>>(x, norm_w, h);
    launch_gemm(h, embed, out, BT, VOCAB, Dm, Dm, Dm, VOCAB, 0,0,0,0,0,0, 1, 1, 0);
}